// round 1
// baseline (speedup 1.0000x reference)
#include <cuda_runtime.h>
#include <cstddef>

// Problem constants (fixed by the reference)
#define B_   32
#define S_   1024
#define D_   1024
#define H_   16
#define NF   48          // H_ * KERNEL(3)
#define BM   128         // rows per block tile
#define BK   32          // k-slice per step
#define NT   256         // threads per block
#define NSTEP (D_ / BK)  // 32

// Scratch: per-batch conv weights W2[b][j=h*3+k][d], 32*48*1024 fp32 = 6 MB
__device__ float g_W2[(size_t)B_ * NF * D_];

// ---- packed fp32x2 helpers (Blackwell FFMA2: 2x fp32 FMA throughput) ----
__device__ __forceinline__ unsigned long long dup2(float a) {
    unsigned long long r;
    asm("mov.b64 %0, {%1, %1};" : "=l"(r) : "f"(a));
    return r;
}
__device__ __forceinline__ void ffma2(unsigned long long& d,
                                      unsigned long long a,
                                      unsigned long long b) {
    asm("fma.rn.f32x2 %0, %1, %2, %3;" : "=l"(d) : "l"(a), "l"(b), "l"(d));
}
__device__ __forceinline__ float2 unpack2(unsigned long long v) {
    float2 r;
    asm("mov.b64 {%0, %1}, %2;" : "=f"(r.x), "=f"(r.y) : "l"(v));
    return r;
}

// =====================================================================
// Kernel 1: qk = Q @ Wq + bq, scattered into g_W2; also zeroes d_out.
// grid = (8, 32): x = row tile (128 rows of s), y = batch
// =====================================================================
__global__ void __launch_bounds__(NT, 2)
qk_gemm_kernel(const float* __restrict__ Q, const float* __restrict__ Wq,
               const float* __restrict__ bq, float* __restrict__ out)
{
    __shared__ __align__(16) float4 As4[BM][8];   // [row][quad], quad col XOR-swizzled
    __shared__ __align__(16) float  Bs[BK][NF];   // [dd][f]

    const int tid = threadIdx.x;
    const int b   = blockIdx.y;
    const int t0  = blockIdx.x * BM;

    // Zero this block's slice of the final output (kernel 2 uses atomics on it)
    {
        float* oz = out + (size_t)b * (H_ * S_) + blockIdx.x * 2048;
        #pragma unroll
        for (int i = 0; i < 8; ++i) oz[i * NT + tid] = 0.0f;
    }

    const float* Ab = Q + (size_t)b * S_ * D_;

    const int lr = tid >> 3;   // 0..31 (A-loader row within pass)
    const int lu = tid & 7;    // 0..7  (A-loader d-quad)
    const int rg = tid >> 2;   // 0..63 (compute row group; TM=2)
    const int cg = tid & 3;    // 0..3  (compute col group; TN=12)
    const int row0 = rg * 2;
    const int row1 = row0 + 1;

    unsigned long long acc[2][6];
    #pragma unroll
    for (int i = 0; i < 2; ++i)
        #pragma unroll
        for (int j = 0; j < 6; ++j) acc[i][j] = 0ULL;

    float4 areg[4];
    float  breg[6];

    // prefetch tile 0
    #pragma unroll
    for (int p = 0; p < 4; ++p)
        areg[p] = *reinterpret_cast<const float4*>(
            Ab + (size_t)(t0 + p * 32 + lr) * D_ + lu * 4);
    #pragma unroll
    for (int i = 0; i < 6; ++i)
        breg[i] = Wq[i * NT + tid];   // Wq is [d][f]: BK rows are contiguous

    #pragma unroll
    for (int p = 0; p < 4; ++p) {
        int r = p * 32 + lr;
        As4[r][lu ^ (r & 7)] = areg[p];
    }
    #pragma unroll
    for (int i = 0; i < 6; ++i) (&Bs[0][0])[i * NT + tid] = breg[i];
    __syncthreads();

    for (int step = 0; step < NSTEP; ++step) {
        const bool more = (step + 1 < NSTEP);
        if (more) {
            const int d0 = (step + 1) * BK;
            #pragma unroll
            for (int p = 0; p < 4; ++p)
                areg[p] = *reinterpret_cast<const float4*>(
                    Ab + (size_t)(t0 + p * 32 + lr) * D_ + d0 + lu * 4);
            #pragma unroll
            for (int i = 0; i < 6; ++i)
                breg[i] = Wq[d0 * NF + i * NT + tid];
        }
        // compute on current smem tile
        #pragma unroll
        for (int q = 0; q < 8; ++q) {
            float4 a0 = As4[row0][q ^ (row0 & 7)];
            float4 a1 = As4[row1][q ^ (row1 & 7)];
            float a0v[4] = {a0.x, a0.y, a0.z, a0.w};
            float a1v[4] = {a1.x, a1.y, a1.z, a1.w};
            #pragma unroll
            for (int w = 0; w < 4; ++w) {
                const ulonglong2* bp =
                    reinterpret_cast<const ulonglong2*>(&Bs[q * 4 + w][cg * 12]);
                ulonglong2 bA = bp[0], bB = bp[1], bC = bp[2];
                unsigned long long u0 = dup2(a0v[w]);
                unsigned long long u1 = dup2(a1v[w]);
                ffma2(acc[0][0], u0, bA.x); ffma2(acc[0][1], u0, bA.y);
                ffma2(acc[0][2], u0, bB.x); ffma2(acc[0][3], u0, bB.y);
                ffma2(acc[0][4], u0, bC.x); ffma2(acc[0][5], u0, bC.y);
                ffma2(acc[1][0], u1, bA.x); ffma2(acc[1][1], u1, bA.y);
                ffma2(acc[1][2], u1, bB.x); ffma2(acc[1][3], u1, bB.y);
                ffma2(acc[1][4], u1, bC.x); ffma2(acc[1][5], u1, bC.y);
            }
        }
        __syncthreads();
        if (more) {
            #pragma unroll
            for (int p = 0; p < 4; ++p) {
                int r = p * 32 + lr;
                As4[r][lu ^ (r & 7)] = areg[p];
            }
            #pragma unroll
            for (int i = 0; i < 6; ++i) (&Bs[0][0])[i * NT + tid] = breg[i];
            __syncthreads();
        }
    }

    // Epilogue: add bias, scatter into W2 per the reshape:
    // e = (s%64)*48 + f; h = s/64; d = e/3; k = e%3; W2[b][h*3+k][d] = qk+bias
    #pragma unroll
    for (int i = 0; i < 2; ++i) {
        const int s = t0 + row0 + i;
        const int h = s >> 6;
        const int ebase = (s & 63) * NF;
        float* w2b = g_W2 + ((size_t)b * NF + h * 3) * D_;
        #pragma unroll
        for (int jp = 0; jp < 6; ++jp) {
            float2 v = unpack2(acc[i][jp]);
            float vv[2] = {v.x, v.y};
            #pragma unroll
            for (int u = 0; u < 2; ++u) {
                const int f = cg * 12 + jp * 2 + u;
                const int e = ebase + f;
                const int d = e / 3;
                const int k = e - d * 3;
                w2b[(size_t)k * D_ + d] = vv[u] + bq[f];
            }
        }
    }
}

// =====================================================================
// Kernel 2: T = K @ W2^T per batch, then 3-tap combine into out.
// out[b,h,s] = T[s-1][3h] + T[s][3h+1] + T[s+1][3h+2]
// =====================================================================
__global__ void __launch_bounds__(NT, 2)
conv_gemm_kernel(const float* __restrict__ Kseq, float* __restrict__ out)
{
    __shared__ __align__(16) float4 As4[BM][8];
    __shared__ __align__(16) float  Bs[BK][NF];   // [dd][j]
    __shared__ __align__(16) float  Ts[BM][NF];   // T tile for the combine

    const int tid = threadIdx.x;
    const int b   = blockIdx.y;
    const int t0  = blockIdx.x * BM;

    const float* Ab = Kseq + (size_t)b * S_ * D_;
    const float* Wb = g_W2 + (size_t)b * NF * D_;   // [j][d]

    const int lr = tid >> 3;
    const int lu = tid & 7;
    const int rg = tid >> 2;
    const int cg = tid & 3;
    const int row0 = rg * 2;
    const int row1 = row0 + 1;

    unsigned long long acc[2][6];
    #pragma unroll
    for (int i = 0; i < 2; ++i)
        #pragma unroll
        for (int j = 0; j < 6; ++j) acc[i][j] = 0ULL;

    float4 areg[4];
    float  breg[6];

    #pragma unroll
    for (int p = 0; p < 4; ++p)
        areg[p] = *reinterpret_cast<const float4*>(
            Ab + (size_t)(t0 + p * 32 + lr) * D_ + lu * 4);
    #pragma unroll
    for (int i = 0; i < 6; ++i) {
        int lin = i * NT + tid;                 // j = lin>>5, dd = lin&31
        breg[i] = Wb[(size_t)(lin >> 5) * D_ + (lin & 31)];
    }

    #pragma unroll
    for (int p = 0; p < 4; ++p) {
        int r = p * 32 + lr;
        As4[r][lu ^ (r & 7)] = areg[p];
    }
    #pragma unroll
    for (int i = 0; i < 6; ++i) {
        int lin = i * NT + tid;
        Bs[lin & 31][lin >> 5] = breg[i];
    }
    __syncthreads();

    for (int step = 0; step < NSTEP; ++step) {
        const bool more = (step + 1 < NSTEP);
        if (more) {
            const int d0 = (step + 1) * BK;
            #pragma unroll
            for (int p = 0; p < 4; ++p)
                areg[p] = *reinterpret_cast<const float4*>(
                    Ab + (size_t)(t0 + p * 32 + lr) * D_ + d0 + lu * 4);
            #pragma unroll
            for (int i = 0; i < 6; ++i) {
                int lin = i * NT + tid;
                breg[i] = Wb[(size_t)(lin >> 5) * D_ + d0 + (lin & 31)];
            }
        }
        #pragma unroll
        for (int q = 0; q < 8; ++q) {
            float4 a0 = As4[row0][q ^ (row0 & 7)];
            float4 a1 = As4[row1][q ^ (row1 & 7)];
            float a0v[4] = {a0.x, a0.y, a0.z, a0.w};
            float a1v[4] = {a1.x, a1.y, a1.z, a1.w};
            #pragma unroll
            for (int w = 0; w < 4; ++w) {
                const ulonglong2* bp =
                    reinterpret_cast<const ulonglong2*>(&Bs[q * 4 + w][cg * 12]);
                ulonglong2 bA = bp[0], bB = bp[1], bC = bp[2];
                unsigned long long u0 = dup2(a0v[w]);
                unsigned long long u1 = dup2(a1v[w]);
                ffma2(acc[0][0], u0, bA.x); ffma2(acc[0][1], u0, bA.y);
                ffma2(acc[0][2], u0, bB.x); ffma2(acc[0][3], u0, bB.y);
                ffma2(acc[0][4], u0, bC.x); ffma2(acc[0][5], u0, bC.y);
                ffma2(acc[1][0], u1, bA.x); ffma2(acc[1][1], u1, bA.y);
                ffma2(acc[1][2], u1, bB.x); ffma2(acc[1][3], u1, bB.y);
                ffma2(acc[1][4], u1, bC.x); ffma2(acc[1][5], u1, bC.y);
            }
        }
        __syncthreads();
        if (more) {
            #pragma unroll
            for (int p = 0; p < 4; ++p) {
                int r = p * 32 + lr;
                As4[r][lu ^ (r & 7)] = areg[p];
            }
            #pragma unroll
            for (int i = 0; i < 6; ++i) {
                int lin = i * NT + tid;
                Bs[lin & 31][lin >> 5] = breg[i];
            }
            __syncthreads();
        }
    }

    // Stage T tile into smem
    #pragma unroll
    for (int i = 0; i < 2; ++i) {
        const int r = row0 + i;
        #pragma unroll
        for (int jp = 0; jp < 6; ++jp)
            *reinterpret_cast<unsigned long long*>(&Ts[r][cg * 12 + jp * 2]) = acc[i][jp];
    }
    __syncthreads();

    // 3-tap combine: each thread owns one head h and 8 consecutive rows.
    // Tile-boundary rows use atomicAdd (out was zeroed in kernel 1).
    const int h  = tid & 15;
    const int r0 = (tid >> 4) * 8;
    const int c0 = 3 * h, c1 = 3 * h + 1, c2 = 3 * h + 2;
    float* orow = out + ((size_t)b * H_ + h) * S_;
    #pragma unroll
    for (int r = 0; r < 8; ++r) {
        const int rr = r0 + r;
        const int s  = t0 + rr;
        if (rr >= 1 && rr <= 126) {
            orow[s] = Ts[rr - 1][c0] + Ts[rr][c1] + Ts[rr + 1][c2];
        } else if (rr == 0) {
            atomicAdd(&orow[s], Ts[0][c1] + Ts[1][c2]);
            if (s > 0) atomicAdd(&orow[s - 1], Ts[0][c2]);
        } else { // rr == 127
            atomicAdd(&orow[s], Ts[126][c0] + Ts[127][c1]);
            if (s < S_ - 1) atomicAdd(&orow[s + 1], Ts[127][c0]);
        }
    }
}

extern "C" void kernel_launch(void* const* d_in, const int* in_sizes, int n_in,
                              void* d_out, int out_size)
{
    (void)in_sizes; (void)n_in; (void)out_size;
    const float* Q   = (const float*)d_in[0];
    const float* Ksq = (const float*)d_in[1];
    // d_in[2] = value_sequences (unused), d_in[3] = kv lengths (unused)
    const float* Wq  = (const float*)d_in[4];
    const float* bq  = (const float*)d_in[5];
    float* out = (float*)d_out;

    dim3 grid(S_ / BM, B_);
    qk_gemm_kernel<<<grid, NT>>>(Q, Wq, bq, out);
    conv_gemm_kernel<<<grid, NT>>>(Ksq, out);
}

// round 2
// speedup vs baseline: 1.3682x; 1.3682x over previous
#include <cuda_runtime.h>
#include <cstddef>

// Problem constants (fixed by the reference)
#define B_   32
#define S_   1024
#define D_   1024
#define H_   16
#define NF   48          // H_ * KERNEL(3)
#define BM   128         // rows per block tile
#define BK   32          // k-slice per step
#define NT   128         // threads per block (4 warps)
#define NSTEP (D_ / BK)  // 32

// Scratch: per-batch conv weights W2[b][j=h*3+k][d], 32*48*1024 fp32 = 6 MB
__device__ float g_W2[(size_t)B_ * NF * D_];

// packed fp32x2 FMA (Blackwell FFMA2): d.lo += a.lo*b.lo ; d.hi += a.hi*b.hi
__device__ __forceinline__ void ffma2(unsigned long long& d,
                                      unsigned long long a,
                                      unsigned long long b) {
    asm("fma.rn.f32x2 %0, %1, %2, %3;" : "=l"(d) : "l"(a), "l"(b), "l"(d));
}
__device__ __forceinline__ float2 unpack2(unsigned long long v) {
    float2 r;
    asm("mov.b64 {%0, %1}, %2;" : "=f"(r.x), "=f"(r.y) : "l"(v));
    return r;
}

// Thread mapping (both kernels):
//   warp w = tid>>5 owns cols [12w, 12w+12)
//   lane    owns rows {lane, lane+32, lane+64, lane+96} (TM=4 layers)
// B reads are warp-uniform (broadcast); A reads hit the 4-phase LDS.128 floor.
// Accumulators are u64 (even-k sum, odd-k sum) -> no dup2 MOVs needed.

// =====================================================================
// Kernel 1: qk = Q @ Wq + bq, scattered into g_W2; also zeroes d_out.
// grid = (8, 32): x = row tile (128 rows of s), y = batch
// =====================================================================
__global__ void __launch_bounds__(NT)
qk_gemm_kernel(const float* __restrict__ Q, const float* __restrict__ Wq,
               const float* __restrict__ bq, float* __restrict__ out)
{
    __shared__ __align__(16) float4 As4[BM][8];    // [row][quad], XOR-swizzled
    __shared__ __align__(16) float  Bs[NF][36];    // [f][k], padded row (144B)

    const int tid  = threadIdx.x;
    const int b    = blockIdx.y;
    const int t0   = blockIdx.x * BM;
    const int lane = tid & 31;
    const int w    = tid >> 5;
    const int c0   = w * 12;

    // Zero this block's slice of the final output (kernel 2 uses atomics on it)
    {
        float* oz = out + (size_t)b * (H_ * S_) + blockIdx.x * 2048;
        #pragma unroll
        for (int i = 0; i < 16; ++i) oz[i * NT + tid] = 0.0f;
    }

    const float* Ab = Q + (size_t)b * S_ * D_;

    // A loader: quad u, base row r16 (8 passes of 16 rows)
    const int lu  = tid & 7;
    const int lr  = tid >> 3;            // 0..15
    // B loader: k row kk, 12-col chunk f0
    const int lkk = tid >> 2;            // 0..31
    const int lf0 = (tid & 3) * 12;

    unsigned long long acc[4][12];
    #pragma unroll
    for (int l = 0; l < 4; ++l)
        #pragma unroll
        for (int c = 0; c < 12; ++c) acc[l][c] = 0ULL;

    float4 areg[8];
    float4 breg[3];

    // ---- prefetch tile 0 ----
    #pragma unroll
    for (int p = 0; p < 8; ++p)
        areg[p] = *reinterpret_cast<const float4*>(
            Ab + (size_t)(t0 + p * 16 + lr) * D_ + lu * 4);
    #pragma unroll
    for (int i = 0; i < 3; ++i)
        breg[i] = *reinterpret_cast<const float4*>(
            Wq + (size_t)lkk * NF + lf0 + i * 4);

    #pragma unroll
    for (int p = 0; p < 8; ++p) {
        int r = p * 16 + lr;
        As4[r][lu ^ (r & 7)] = areg[p];
    }
    {
        const float* bv = reinterpret_cast<const float*>(breg);
        #pragma unroll
        for (int i = 0; i < 12; ++i) Bs[lf0 + i][lkk] = bv[i];
    }
    __syncthreads();

    for (int step = 0; step < NSTEP; ++step) {
        const bool more = (step + 1 < NSTEP);
        if (more) {
            const int d0 = (step + 1) * BK;
            #pragma unroll
            for (int p = 0; p < 8; ++p)
                areg[p] = *reinterpret_cast<const float4*>(
                    Ab + (size_t)(t0 + p * 16 + lr) * D_ + d0 + lu * 4);
            #pragma unroll
            for (int i = 0; i < 3; ++i)
                breg[i] = *reinterpret_cast<const float4*>(
                    Wq + (size_t)(d0 + lkk) * NF + lf0 + i * 4);
        }
        // ---- compute on current smem tile ----
        #pragma unroll
        for (int q = 0; q < 8; ++q) {
            ulonglong2 a2[4];
            #pragma unroll
            for (int l = 0; l < 4; ++l)
                a2[l] = *reinterpret_cast<const ulonglong2*>(
                    &As4[l * 32 + lane][q ^ (lane & 7)]);
            #pragma unroll
            for (int c = 0; c < 12; ++c) {
                ulonglong2 b2 = *reinterpret_cast<const ulonglong2*>(
                    &Bs[c0 + c][q * 4]);
                #pragma unroll
                for (int l = 0; l < 4; ++l) {
                    ffma2(acc[l][c], a2[l].x, b2.x);
                    ffma2(acc[l][c], a2[l].y, b2.y);
                }
            }
        }
        __syncthreads();
        if (more) {
            #pragma unroll
            for (int p = 0; p < 8; ++p) {
                int r = p * 16 + lr;
                As4[r][lu ^ (r & 7)] = areg[p];
            }
            const float* bv = reinterpret_cast<const float*>(breg);
            #pragma unroll
            for (int i = 0; i < 12; ++i) Bs[lf0 + i][lkk] = bv[i];
            __syncthreads();
        }
    }

    // Epilogue: add bias, scatter into W2 per the reshape:
    // e = (s%64)*48 + f; h = s/64; d = e/3; k = e%3; W2[b][h*3+k][d] = qk+bias
    #pragma unroll
    for (int l = 0; l < 4; ++l) {
        const int s = t0 + l * 32 + lane;
        const int h = s >> 6;
        const int ebase = (s & 63) * NF;
        float* w2b = g_W2 + ((size_t)b * NF + h * 3) * D_;
        #pragma unroll
        for (int c = 0; c < 12; ++c) {
            const int f = c0 + c;
            float2 v = unpack2(acc[l][c]);
            const int e = ebase + f;
            const int d = e / 3;
            const int k = e - d * 3;
            w2b[(size_t)k * D_ + d] = v.x + v.y + __ldg(&bq[f]);
        }
    }
}

// =====================================================================
// Kernel 2: T = K @ W2^T per batch, then 3-tap combine into out.
// out[b,h,s] = T[s-1][3h] + T[s][3h+1] + T[s+1][3h+2]
// =====================================================================
__global__ void __launch_bounds__(NT)
conv_gemm_kernel(const float* __restrict__ Kseq, float* __restrict__ out)
{
    __shared__ __align__(16) float4 As4[BM][8];
    __shared__ __align__(16) float  Bs[NF][36];    // [j][k], padded row
    __shared__ __align__(16) float  Ts[BM][49];    // T tile for combine (padded)

    const int tid  = threadIdx.x;
    const int b    = blockIdx.y;
    const int t0   = blockIdx.x * BM;
    const int lane = tid & 31;
    const int w    = tid >> 5;
    const int c0   = w * 12;

    const float* Ab = Kseq + (size_t)b * S_ * D_;
    const float* Wb = g_W2 + (size_t)b * NF * D_;   // [j][d], d contiguous

    const int lu = tid & 7;
    const int lr = tid >> 3;

    unsigned long long acc[4][12];
    #pragma unroll
    for (int l = 0; l < 4; ++l)
        #pragma unroll
        for (int c = 0; c < 12; ++c) acc[l][c] = 0ULL;

    float4 areg[8];
    float4 breg[3];

    // ---- prefetch tile 0 ----
    #pragma unroll
    for (int p = 0; p < 8; ++p)
        areg[p] = *reinterpret_cast<const float4*>(
            Ab + (size_t)(t0 + p * 16 + lr) * D_ + lu * 4);
    #pragma unroll
    for (int i = 0; i < 3; ++i) {
        int f4 = tid + i * NT;             // 0..383
        int j  = f4 >> 3, qd = f4 & 7;
        breg[i] = *reinterpret_cast<const float4*>(Wb + (size_t)j * D_ + qd * 4);
    }

    #pragma unroll
    for (int p = 0; p < 8; ++p) {
        int r = p * 16 + lr;
        As4[r][lu ^ (r & 7)] = areg[p];
    }
    #pragma unroll
    for (int i = 0; i < 3; ++i) {
        int f4 = tid + i * NT;
        int j  = f4 >> 3, qd = f4 & 7;
        *reinterpret_cast<float4*>(&Bs[j][qd * 4]) = breg[i];
    }
    __syncthreads();

    for (int step = 0; step < NSTEP; ++step) {
        const bool more = (step + 1 < NSTEP);
        if (more) {
            const int d0 = (step + 1) * BK;
            #pragma unroll
            for (int p = 0; p < 8; ++p)
                areg[p] = *reinterpret_cast<const float4*>(
                    Ab + (size_t)(t0 + p * 16 + lr) * D_ + d0 + lu * 4);
            #pragma unroll
            for (int i = 0; i < 3; ++i) {
                int f4 = tid + i * NT;
                int j  = f4 >> 3, qd = f4 & 7;
                breg[i] = *reinterpret_cast<const float4*>(
                    Wb + (size_t)j * D_ + d0 + qd * 4);
            }
        }
        #pragma unroll
        for (int q = 0; q < 8; ++q) {
            ulonglong2 a2[4];
            #pragma unroll
            for (int l = 0; l < 4; ++l)
                a2[l] = *reinterpret_cast<const ulonglong2*>(
                    &As4[l * 32 + lane][q ^ (lane & 7)]);
            #pragma unroll
            for (int c = 0; c < 12; ++c) {
                ulonglong2 b2 = *reinterpret_cast<const ulonglong2*>(
                    &Bs[c0 + c][q * 4]);
                #pragma unroll
                for (int l = 0; l < 4; ++l) {
                    ffma2(acc[l][c], a2[l].x, b2.x);
                    ffma2(acc[l][c], a2[l].y, b2.y);
                }
            }
        }
        __syncthreads();
        if (more) {
            #pragma unroll
            for (int p = 0; p < 8; ++p) {
                int r = p * 16 + lr;
                As4[r][lu ^ (r & 7)] = areg[p];
            }
            #pragma unroll
            for (int i = 0; i < 3; ++i) {
                int f4 = tid + i * NT;
                int j  = f4 >> 3, qd = f4 & 7;
                *reinterpret_cast<float4*>(&Bs[j][qd * 4]) = breg[i];
            }
            __syncthreads();
        }
    }

    // Stage T tile into smem
    #pragma unroll
    for (int l = 0; l < 4; ++l) {
        const int r = l * 32 + lane;
        #pragma unroll
        for (int c = 0; c < 12; ++c) {
            float2 v = unpack2(acc[l][c]);
            Ts[r][c0 + c] = v.x + v.y;
        }
    }
    __syncthreads();

    // 3-tap combine: each thread owns one head h and 16 consecutive rows.
    // Tile-boundary rows use atomicAdd (out was zeroed in kernel 1).
    const int h  = tid & 15;
    const int r0 = (tid >> 4) * 16;
    const int cc0 = 3 * h, cc1 = 3 * h + 1, cc2 = 3 * h + 2;
    float* orow = out + ((size_t)b * H_ + h) * S_;
    #pragma unroll
    for (int r = 0; r < 16; ++r) {
        const int rr = r0 + r;
        const int s  = t0 + rr;
        if (rr >= 1 && rr <= 126) {
            orow[s] = Ts[rr - 1][cc0] + Ts[rr][cc1] + Ts[rr + 1][cc2];
        } else if (rr == 0) {
            atomicAdd(&orow[s], Ts[0][cc1] + Ts[1][cc2]);
            if (s > 0) atomicAdd(&orow[s - 1], Ts[0][cc2]);
        } else { // rr == 127
            atomicAdd(&orow[s], Ts[126][cc0] + Ts[127][cc1]);
            if (s < S_ - 1) atomicAdd(&orow[s + 1], Ts[127][cc0]);
        }
    }
}

extern "C" void kernel_launch(void* const* d_in, const int* in_sizes, int n_in,
                              void* d_out, int out_size)
{
    (void)in_sizes; (void)n_in; (void)out_size;
    const float* Q   = (const float*)d_in[0];
    const float* Ksq = (const float*)d_in[1];
    // d_in[2] = value_sequences (unused), d_in[3] = kv lengths (unused)
    const float* Wq  = (const float*)d_in[4];
    const float* bq  = (const float*)d_in[5];
    float* out = (float*)d_out;

    dim3 grid(S_ / BM, B_);
    qk_gemm_kernel<<<grid, NT>>>(Q, Wq, bq, out);
    conv_gemm_kernel<<<grid, NT>>>(Ksq, out);
}

// round 4
// speedup vs baseline: 2.1182x; 1.5482x over previous
#include <cuda_runtime.h>
#include <cuda_bf16.h>
#include <cstdint>
#include <cstddef>

// Problem constants
#define B_   32
#define S_   1024
#define D_   1024
#define H_   16
#define NF   48
#define BM   128          // M tile per CTA
#define BKC  64           // k per chunk (row = 128 B in bf16)
#define NCHUNK (D_ / BKC) // 16
#define NT   256          // 8 warps

// ---------------- scratch (device globals; no allocations) ----------------
__device__ __align__(16) __nv_bfloat16 g_Wqt_h[NF * D_];
__device__ __align__(16) __nv_bfloat16 g_Wqt_l[NF * D_];
__device__ __align__(16) __nv_bfloat16 g_W2_h[(size_t)B_ * NF * D_];
__device__ __align__(16) __nv_bfloat16 g_W2_l[(size_t)B_ * NF * D_];

// ---------------- helpers ----------------
__device__ __forceinline__ uint32_t smem_u32(const void* p) {
    uint32_t a;
    asm("{ .reg .u64 t; cvta.to.shared.u64 t, %1; cvt.u32.u64 %0, t; }" : "=r"(a) : "l"(p));
    return a;
}
// swizzle within a 128-byte row: for o = r*128 + c*16 -> c ^= (r & 7)
#define SWZ(o) ((o) ^ (((o) >> 3) & 0x70))

#define CP_ASYNC16(s, g) \
    asm volatile("cp.async.cg.shared.global [%0], [%1], 16;" :: "r"(s), "l"(g) : "memory")
#define CP_COMMIT() asm volatile("cp.async.commit_group;" ::: "memory")
#define CP_WAIT0()  asm volatile("cp.async.wait_group 0;" ::: "memory")

__device__ __forceinline__ void ldsm4(uint32_t* r, uint32_t addr) {
    asm volatile("ldmatrix.sync.aligned.m8n8.x4.shared.b16 {%0,%1,%2,%3}, [%4];"
                 : "=r"(r[0]), "=r"(r[1]), "=r"(r[2]), "=r"(r[3]) : "r"(addr));
}
__device__ __forceinline__ void mma_bf16(float* c, const uint32_t* a, const uint32_t* b) {
    asm volatile(
        "mma.sync.aligned.m16n8k16.row.col.f32.bf16.bf16.f32 "
        "{%0,%1,%2,%3}, {%4,%5,%6,%7}, {%8,%9}, {%0,%1,%2,%3};"
        : "+f"(c[0]), "+f"(c[1]), "+f"(c[2]), "+f"(c[3])
        : "r"(a[0]), "r"(a[1]), "r"(a[2]), "r"(a[3]), "r"(b[0]), "r"(b[1]));
}
// packed (x0, x1) -> bf16x2 with x0 in low half
__device__ __forceinline__ uint32_t cvt_bf16x2(float x0, float x1) {
    uint32_t r;
    asm("cvt.rn.bf16x2.f32 %0, %1, %2;" : "=r"(r) : "f"(x1), "f"(x0));
    return r;
}
#define STS128(addr, r0, r1, r2, r3) \
    asm volatile("st.shared.v4.b32 [%0], {%1,%2,%3,%4};" \
                 :: "r"(addr), "r"(r0), "r"(r1), "r"(r2), "r"(r3) : "memory")

// ---------------- smem layout ----------------
#define SM_A_H  0                       // 128 x 64 bf16 = 16384
#define SM_A_L  16384
#define SM_B    32768                   // 2 bufs x (h,l) x 48 x 64 bf16
#define SM_BBUF 12288
#define SM_BHL  6144
#define SM_TOTAL 57344
// Ts (G2 combine tile) aliases A region: 128 x 52 fp32 = 26624 bytes

// =====================================================================
// Prep: transpose + bf16-split Wq[d][f] -> g_Wqt_{h,l}[f][d]
// =====================================================================
__global__ void prep_kernel(const float* __restrict__ Wq) {
    const int f = blockIdx.x;
    for (int d = threadIdx.x; d < D_; d += blockDim.x) {
        float x = Wq[(size_t)d * NF + f];
        __nv_bfloat16 h = __float2bfloat16(x);
        g_Wqt_h[f * D_ + d] = h;
        g_Wqt_l[f * D_ + d] = __float2bfloat16(x - __bfloat162float(h));
    }
}

// =====================================================================
// Unified GEMM (bf16x3 split, mma.sync m16n8k16).
//   G1: T = Q @ Wqt^T + bq -> scatter into g_W2_{h,l}; zero out
//   G2: T = K @ W2^T       -> 3-tap combine into out
// grid = (8, 32), 8 warps: warp w owns rows [16w,16w+16), all N=48
// =====================================================================
template <bool G1>
__global__ void __launch_bounds__(NT, 2)
gemm_kernel(const float* __restrict__ Aglob, const float* __restrict__ bq,
            float* __restrict__ out)
{
    extern __shared__ char smem[];
    const uint32_t sb = smem_u32(smem);
    const int tid  = threadIdx.x;
    const int b    = blockIdx.y;
    const int t0   = blockIdx.x * BM;
    const int wid  = tid >> 5;
    const int lane = tid & 31;

    if (G1) {  // zero this block's slice of out (G2 boundary atomics need 0)
        float* oz = out + (size_t)b * (H_ * S_) + blockIdx.x * 2048;
        #pragma unroll
        for (int i = 0; i < 8; ++i) oz[i * NT + tid] = 0.0f;
    }

    const float* Ab = Aglob + ((size_t)b * S_ + t0) * D_;
    const __nv_bfloat16* Bh = G1 ? g_Wqt_h : (g_W2_h + (size_t)b * NF * D_);
    const __nv_bfloat16* Bl = G1 ? g_Wqt_l : (g_W2_l + (size_t)b * NF * D_);

    // A staging: thread -> (row ar, k-half ah)
    const int ar = tid >> 1;
    const int ah = (tid & 1) * 32;
    float4 areg[8];

    // ldmatrix lane geometry
    const int m0    = wid * 16;
    const int row_a = m0 + (lane & 15);
    const int kb_a  = lane >> 4;             // k 16B-chunk parity for A
    const uint32_t a_rb = (uint32_t)(row_a * 128);
    const int xa    = row_a & 7;
    const int rb0   = (lane & 7) + ((lane >> 4) << 3);   // B row within 16-row pair
    const int kb_b  = (lane >> 3) & 1;
    const int xb    = lane & 7;

    float acc[6][4];
    #pragma unroll
    for (int t = 0; t < 6; ++t)
        #pragma unroll
        for (int i = 0; i < 4; ++i) acc[t][i] = 0.0f;

    auto cpB = [&](int c, int buf) {
        #pragma unroll
        for (int u = 0; u < 3; ++u) {
            int gi = tid + u * NT;           // 0..767 = (h,l) x 48 rows x 8 chunks
            int hl = (gi >= 384);
            int e  = hl ? gi - 384 : gi;
            int row = e >> 3, j = e & 7;
            uint32_t saddr = sb + SM_B + buf * SM_BBUF + hl * SM_BHL
                           + SWZ((uint32_t)(row * 128 + j * 16));
            const __nv_bfloat16* g = (hl ? Bl : Bh) + (size_t)row * D_ + c * BKC + j * 8;
            CP_ASYNC16(saddr, g);
        }
    };
    auto lda = [&](int c) {
        const float* p = Ab + (size_t)ar * D_ + c * BKC + ah;
        #pragma unroll
        for (int j = 0; j < 8; ++j)
            areg[j] = *reinterpret_cast<const float4*>(p + j * 4);
    };
    auto sta = [&]() {
        #pragma unroll
        for (int g = 0; g < 4; ++g) {
            float xs[8];
            float4 u = areg[2 * g], v = areg[2 * g + 1];
            xs[0]=u.x; xs[1]=u.y; xs[2]=u.z; xs[3]=u.w;
            xs[4]=v.x; xs[5]=v.y; xs[6]=v.z; xs[7]=v.w;
            uint32_t hw[4], lw[4];
            #pragma unroll
            for (int p = 0; p < 4; ++p) {
                uint32_t hp = cvt_bf16x2(xs[2*p], xs[2*p+1]);
                float h0 = __uint_as_float(hp << 16);
                float h1 = __uint_as_float(hp & 0xFFFF0000u);
                hw[p] = hp;
                lw[p] = cvt_bf16x2(xs[2*p] - h0, xs[2*p+1] - h1);
            }
            uint32_t off = SWZ((uint32_t)(ar * 128 + (ah + g * 8) * 2));
            STS128(sb + SM_A_H + off, hw[0], hw[1], hw[2], hw[3]);
            STS128(sb + SM_A_L + off, lw[0], lw[1], lw[2], lw[3]);
        }
    };
    auto compute = [&](int buf) {
        const uint32_t bb_h = sb + SM_B + buf * SM_BBUF;
        const uint32_t bb_l = bb_h + SM_BHL;
        #pragma unroll
        for (int s = 0; s < 4; ++s) {
            uint32_t a_h[4], a_l[4];
            uint32_t co_a = (uint32_t)(((2 * s + kb_a) ^ xa) << 4);
            ldsm4(a_h, sb + SM_A_H + a_rb + co_a);
            ldsm4(a_l, sb + SM_A_L + a_rb + co_a);
            uint32_t co_b = (uint32_t)(((2 * s + kb_b) ^ xb) << 4);
            #pragma unroll
            for (int tp = 0; tp < 3; ++tp) {
                uint32_t ro = (uint32_t)((rb0 + 16 * tp) * 128);
                uint32_t bh4[4], bl4[4];
                ldsm4(bh4, bb_h + ro + co_b);
                ldsm4(bl4, bb_l + ro + co_b);
                #pragma unroll
                for (int tt = 0; tt < 2; ++tt) {
                    float* a6 = acc[2 * tp + tt];
                    mma_bf16(a6, a_h, bh4 + 2 * tt);
                    mma_bf16(a6, a_h, bl4 + 2 * tt);
                    mma_bf16(a6, a_l, bh4 + 2 * tt);
                }
            }
        }
    };

    // ---- prologue ----
    cpB(0, 0); CP_COMMIT();
    lda(0);
    sta();
    CP_WAIT0();
    __syncthreads();

    // ---- main loop: A single-buffer (reg prefetch), B double-buffer (cp.async)
    for (int c = 0; c < NCHUNK; ++c) {
        const int buf = c & 1;
        if (c + 1 < NCHUNK) {
            cpB(c + 1, buf ^ 1); CP_COMMIT();
            lda(c + 1);
        }
        compute(buf);
        __syncthreads();
        if (c + 1 < NCHUNK) {
            sta();
            CP_WAIT0();
            __syncthreads();
        }
    }

    // ---- epilogue ----
    const int lq  = lane >> 2;        // row within m8
    const int lc2 = (lane & 3) * 2;   // col pair base

    if (G1) {
        // bias + bf16-split scatter into W2 (reshape: e=(s%64)*48+f, d=e/3, k=e%3)
        #pragma unroll
        for (int half = 0; half < 2; ++half) {
            const int rr = m0 + lq + half * 8;
            const int s  = t0 + rr;
            const int hh = s >> 6;
            const int ebase = (s & 63) * NF;
            const size_t base = ((size_t)b * NF + hh * 3) * D_;
            #pragma unroll
            for (int t = 0; t < 6; ++t)
                #pragma unroll
                for (int i = 0; i < 2; ++i) {
                    const int f = 8 * t + lc2 + i;
                    float v = acc[t][half * 2 + i] + __ldg(&bq[f]);
                    __nv_bfloat16 vh = __float2bfloat16(v);
                    __nv_bfloat16 vl = __float2bfloat16(v - __bfloat162float(vh));
                    const int e = ebase + f;
                    const int d = e / 3, k = e - d * 3;
                    g_W2_h[base + (size_t)k * D_ + d] = vh;
                    g_W2_l[base + (size_t)k * D_ + d] = vl;
                }
        }
    } else {
        // stage T tile into smem (aliases A region), then 3-tap combine
        float* ts = reinterpret_cast<float*>(smem);
        __syncthreads();
        #pragma unroll
        for (int half = 0; half < 2; ++half) {
            const int rr = m0 + lq + half * 8;
            #pragma unroll
            for (int t = 0; t < 6; ++t) {
                ts[rr * 52 + 8 * t + lc2]     = acc[t][half * 2];
                ts[rr * 52 + 8 * t + lc2 + 1] = acc[t][half * 2 + 1];
            }
        }
        __syncthreads();
        const int hh = tid & 15;
        const int r0 = (tid >> 4) * 8;
        const int cc0 = 3 * hh, cc1 = cc0 + 1, cc2 = cc0 + 2;
        float* orow = out + ((size_t)b * H_ + hh) * S_;
        #pragma unroll
        for (int r = 0; r < 8; ++r) {
            const int rr = r0 + r;
            const int s  = t0 + rr;
            if (rr >= 1 && rr <= 126) {
                orow[s] = ts[(rr - 1) * 52 + cc0] + ts[rr * 52 + cc1] + ts[(rr + 1) * 52 + cc2];
            } else if (rr == 0) {
                atomicAdd(&orow[s], ts[cc1] + ts[52 + cc2]);
                if (s > 0) atomicAdd(&orow[s - 1], ts[cc2]);
            } else { // rr == 127
                atomicAdd(&orow[s], ts[126 * 52 + cc0] + ts[127 * 52 + cc1]);
                if (s < S_ - 1) atomicAdd(&orow[s + 1], ts[127 * 52 + cc0]);
            }
        }
    }
}

extern "C" void kernel_launch(void* const* d_in, const int* in_sizes, int n_in,
                              void* d_out, int out_size)
{
    (void)in_sizes; (void)n_in; (void)out_size;
    const float* Q   = (const float*)d_in[0];
    const float* Ksq = (const float*)d_in[1];
    const float* Wq  = (const float*)d_in[4];
    const float* bq  = (const float*)d_in[5];
    float* out = (float*)d_out;

    static bool attr_done = false;
    if (!attr_done) {
        cudaFuncSetAttribute(gemm_kernel<true>,
                             cudaFuncAttributeMaxDynamicSharedMemorySize, SM_TOTAL);
        cudaFuncSetAttribute(gemm_kernel<false>,
                             cudaFuncAttributeMaxDynamicSharedMemorySize, SM_TOTAL);
        attr_done = true;
    }

    dim3 grid(S_ / BM, B_);
    prep_kernel<<<NF, 256>>>(Wq);
    gemm_kernel<true><<<grid, NT, SM_TOTAL>>>(Q, bq, out);
    gemm_kernel<false><<<grid, NT, SM_TOTAL>>>(Ksq, bq, out);
}